// round 13
// baseline (speedup 1.0000x reference)
#include <cuda_runtime.h>
#include <math.h>

#define CHN 143
#define NT  128

// Packed weights (float4 per (cout,cin) triple, 4th lane = 0).
// Layout (float4 units): W1@0(32), W2@32(448), W3@480(784), W4@1264(784),
//                        F1@2048(8), F2@2056(16), F3@2072(16), F4@2088(16)
__device__ float4 g_Wp[2104];

__device__ __forceinline__ void copy3(float* dst, const float* src) {
    dst[0] = src[0]; dst[1] = src[1]; dst[2] = src[2]; dst[3] = 0.f;
}

__global__ void init_pack(const float* w1, const float* w2, const float* w3, const float* w4,
                          const float* f1, const float* f2, const float* f3, const float* f4)
{
    int tid = threadIdx.x;
    float* g = (float*)g_Wp;
    for (int e = tid; e < 32;  e += 256) copy3(g + (0    + e) * 4, w1 + e * 3);
    for (int e = tid; e < 448; e += 256) copy3(g + (32   + e) * 4, w2 + e * 3);
    for (int e = tid; e < 784; e += 256) copy3(g + (480  + e) * 4, w3 + e * 3);
    for (int e = tid; e < 784; e += 256) copy3(g + (1264 + e) * 4, w4 + e * 3);
    for (int e = tid; e < 8;   e += 256) copy3(g + (2048 + e) * 4, f1 + e * 3);
    for (int e = tid; e < 16;  e += 256) copy3(g + (2056 + e) * 4, f2 + e * 3);
    for (int e = tid; e < 16;  e += 256) copy3(g + (2072 + e) * 4, f3 + e * 3);
    for (int e = tid; e < 16;  e += 256) copy3(g + (2088 + e) * 4, f4 + e * 3);
}

// One DFT bin task via rotation recurrence: u in [0,144) -> (vector c, bin k).
// Writes |X[k]| and |X[143-k]|. No twiddle table: rot_{n+1} = rot_n * w^k.
__device__ __forceinline__ void dft_one(int u, const float* rawp, float* vinp)
{
    int c = (u >= 72) ? 1 : 0;
    int k = u - 72 * c;
    const float* v = rawp + c * 144;
    float si, co;
    sincosf(-6.28318530717958647692f * (float)k / 143.0f, &si, &co);
    float rr = 1.f, ri = 0.f, re = 0.f, im = 0.f;
#pragma unroll 13
    for (int n = 0; n < 143; n++) {
        float val = v[n];
        re = fmaf(rr, val, re);
        im = fmaf(ri, val, im);
        float nr = fmaf(rr, co, -ri * si);
        float ni = fmaf(rr, si,  ri * co);
        rr = nr; ri = ni;
    }
    float mag = sqrtf(fmaf(re, re, im * im));
    vinp[c * 144 + k] = mag;
    if (k) vinp[c * 144 + 143 - k] = mag;
}

// Conv1d(k=3,s=2,VALID) + LayerNorm + ReLU, pair-of-outputs layout.
// Lane owns output pairs (2P, 2P+1), P = lane + 32p. One LDS.128 gives
// row[4P..4P+3]; the straddle element row[4P+4] comes from the next lane's
// .x via shuffle. Warp w owns channels c = w + 4r. Weights amortized over M.
// RowStride must be a multiple of 4 floats; padding garbage only reaches
// masked outputs (excluded from LN sums, never stored).
template<int Cin, int Cout, int RowStride, int Lout, int NP, int M>
__device__ __forceinline__ void convP(
    const float* __restrict__ in, int inStride,
    float* __restrict__ out, int outRow, int outStride,
    const float4* __restrict__ Wp,
    const float* __restrict__ gam, const float* __restrict__ bet,
    int warp, int lane)
{
    constexpr int ROWS  = Cout / 4;
    constexpr int LOADP = RowStride / 4;
    float a0[ROWS][M][NP], a1[ROWS][M][NP];
#pragma unroll
    for (int r = 0; r < ROWS; r++)
#pragma unroll
        for (int m = 0; m < M; m++)
#pragma unroll
            for (int p = 0; p < NP; p++) { a0[r][m][p] = 0.f; a1[r][m][p] = 0.f; }

#pragma unroll 2
    for (int ic = 0; ic < Cin; ic++) {
        float4 v[M][NP]; float ev[M][NP];
#pragma unroll
        for (int m = 0; m < M; m++) {
            const float* row = in + m * inStride + ic * RowStride;
#pragma unroll
            for (int p = 0; p < NP; p++) {
                int P = lane + 32 * p;
                v[m][p] = (P < LOADP) ? *(const float4*)(row + 4 * P)
                                      : make_float4(0.f, 0.f, 0.f, 0.f);
            }
        }
#pragma unroll
        for (int m = 0; m < M; m++)
#pragma unroll
            for (int p = 0; p < NP; p++) {
                float dn = __shfl_down_sync(0xffffffffu, v[m][p].x, 1);
                if (NP > 1) {
                    float nx = __shfl_sync(0xffffffffu,
                                           (p + 1 < NP) ? v[m][p + 1].x : 0.f, 0);
                    ev[m][p] = (lane == 31) ? nx : dn;
                } else {
                    ev[m][p] = dn;
                }
            }
#pragma unroll
        for (int r = 0; r < ROWS; r++) {
            int c = warp + 4 * r;
            float4 w = __ldg(Wp + c * Cin + ic);
#pragma unroll
            for (int m = 0; m < M; m++)
#pragma unroll
                for (int p = 0; p < NP; p++) {
                    a0[r][m][p] = fmaf(w.x, v[m][p].x, a0[r][m][p]);
                    a0[r][m][p] = fmaf(w.y, v[m][p].y, a0[r][m][p]);
                    a0[r][m][p] = fmaf(w.z, v[m][p].z, a0[r][m][p]);
                    a1[r][m][p] = fmaf(w.x, v[m][p].z, a1[r][m][p]);
                    a1[r][m][p] = fmaf(w.y, v[m][p].w, a1[r][m][p]);
                    a1[r][m][p] = fmaf(w.z, ev[m][p],  a1[r][m][p]);
                }
        }
    }

    float g0[NP], g1[NP], b0[NP], b1[NP];
#pragma unroll
    for (int p = 0; p < NP; p++) {
        int l = 2 * (lane + 32 * p);
        g0[p] = (l     < Lout) ? __ldg(gam + l)     : 0.f;
        b0[p] = (l     < Lout) ? __ldg(bet + l)     : 0.f;
        g1[p] = (l + 1 < Lout) ? __ldg(gam + l + 1) : 0.f;
        b1[p] = (l + 1 < Lout) ? __ldg(bet + l + 1) : 0.f;
    }
    const float invL = 1.0f / (float)Lout;

#pragma unroll
    for (int r = 0; r < ROWS; r++) {
        int c = warp + 4 * r;
#pragma unroll
        for (int m = 0; m < M; m++) {
            float s = 0.f;
#pragma unroll
            for (int p = 0; p < NP; p++) {
                int l = 2 * (lane + 32 * p);
                if (l     < Lout) s += a0[r][m][p];
                if (l + 1 < Lout) s += a1[r][m][p];
            }
#pragma unroll
            for (int o = 16; o; o >>= 1) s += __shfl_xor_sync(0xffffffffu, s, o);
            float mu = s * invL;

            float s2 = 0.f;
#pragma unroll
            for (int p = 0; p < NP; p++) {
                int l = 2 * (lane + 32 * p);
                if (l < Lout)     { float d = a0[r][m][p] - mu; s2 = fmaf(d, d, s2); }
                if (l + 1 < Lout) { float d = a1[r][m][p] - mu; s2 = fmaf(d, d, s2); }
            }
#pragma unroll
            for (int o = 16; o; o >>= 1) s2 += __shfl_xor_sync(0xffffffffu, s2, o);
            float inv = rsqrtf(fmaf(s2, invL, 1e-5f));

            float* orow = out + m * outStride + c * outRow;
#pragma unroll
            for (int p = 0; p < NP; p++) {
                int P = lane + 32 * p;
                int l = 2 * P;
                float o0 = fmaxf(fmaf((a0[r][m][p] - mu) * inv, g0[p], b0[p]), 0.f);
                float o1 = fmaxf(fmaf((a1[r][m][p] - mu) * inv, g1[p], b1[p]), 0.f);
                if (l + 1 < Lout) {
                    float2 t; t.x = o0; t.y = o1;
                    *(float2*)(orow + l) = t;
                } else if (l < Lout) {
                    orow[l] = o0;
                }
            }
        }
    }
}

// Block = (b, stream, m-half): processes MB=4 samples.
#define MB 4
#define RAW_S 288    // per-sample raw stride (2 x 144)
#define A_S   1152   // 16*72 stage-1 output
#define B_S   1008   // 28*36 stage-2 output
#define C_S   560    // 28*20 stage-3 output (rows padded 18->20)
#define D_S   224    // 28*8  stage-4 output

__global__ void __launch_bounds__(NT, 5)
spectral_kernel(const float* __restrict__ x, float* __restrict__ out,
                const float* __restrict__ ln1w, const float* __restrict__ ln1b,
                const float* __restrict__ ln2w, const float* __restrict__ ln2b,
                const float* __restrict__ ln3w, const float* __restrict__ ln3b,
                const float* __restrict__ ln4w, const float* __restrict__ ln4b)
{
    __shared__ __align__(16) float bufA[MB * A_S];   // 18432 B
    __shared__ __align__(16) float bufB[MB * B_S];   // 16128 B
    // raw/vin alias into bufB: both dead before stage 2 writes bufB.
    float* raw_s = bufB;               // MB * 288 floats
    float* vin_s = bufB + MB * RAW_S;  // MB * 288 floats (total 2304 <= 4032)

    int tid  = threadIdx.x;
    int lane = tid & 31, warp = tid >> 5;
    unsigned blk = blockIdx.x;
    int b      = (int)(blk >> 3);
    int rem    = (int)(blk & 7);
    int stream = rem >> 1;         // 0=cr, 1=cc, 2=cr_fft, 3=cc_fft
    int mbase  = (rem & 1) * MB;   // 0 or 4
    bool isfft = (stream >= 2);
    bool isrow = (stream == 0 || stream == 2);

    const float* xb = x + (size_t)b * (CHN * 64);

    // ---- gather MB (2,143) samples into smem ----
    // cr/cr_fft: sample m -> h = 3 + (m>>2), channels w = 2*(m&3) + c
    // cc/cc_fft: sample m -> h = m,          channels w = 3 + c
    for (int t = tid; t < MB * 286; t += NT) {
        int s = t / 286; int q = t - s * 286;
        int c = (q >= 143); int ch = q - 143 * c;
        int m = mbase + s;
        int base = isrow ? ((3 + (m >> 2)) * 8 + (m & 3) * 2)
                         : (m * 8 + 3);
        raw_s[s * RAW_S + c * 144 + ch] = __ldg(xb + ch * 64 + base + c);
    }
    __syncthreads();

    // ---- DFT magnitude (fft streams only) ----
    if (isfft) {
        for (int t = tid; t < MB * 144; t += NT) {
            int s = t / 144; int u = t - s * 144;
            dft_one(u, raw_s + s * RAW_S, vin_s + s * RAW_S);
        }
        __syncthreads();
    }

    const float* cin = isfft ? vin_s : raw_s;

    if (!isfft) {
        // stage 1 per-sample (weights tiny; keeps register peak low)
#pragma unroll
        for (int s = 0; s < MB; s++)
            convP<2, 16, 144, 71, 2, 1>(cin + s * RAW_S, RAW_S,
                                        bufA + s * A_S, 72, A_S,
                                        g_Wp + 0, ln1w, ln1b, warp, lane);
        __syncthreads();
        convP<16, 28, 72, 35, 1, MB>(bufA, A_S, bufB, 36, B_S,
                                     g_Wp + 32,   ln2w, ln2b, warp, lane);
        __syncthreads();
        convP<28, 28, 36, 17, 1, MB>(bufB, B_S, bufA, 20, C_S,
                                     g_Wp + 480,  ln3w, ln3b, warp, lane);
        __syncthreads();
        convP<28, 28, 20,  8, 1, MB>(bufA, C_S, bufB, 8, D_S,
                                     g_Wp + 1264, ln4w, ln4b, warp, lane);
        __syncthreads();
        int cbase = stream * 28;                       // 0 or 28
        size_t obase = (size_t)b * 4096 + (size_t)cbase * 64;
        for (int t = tid; t < MB * 224; t += NT) {
            int s = t / 224; int q = t - s * 224;
            int c = q >> 3, j = q & 7;
            out[obase + (size_t)c * 64 + (size_t)(mbase + s) * 8 + j] = bufB[s * D_S + q];
        }
    } else {
#pragma unroll
        for (int s = 0; s < MB; s++)
            convP<2, 4, 144, 71, 2, 1>(cin + s * RAW_S, RAW_S,
                                       bufA + s * A_S, 72, A_S,
                                       g_Wp + 2048, ln1w, ln1b, warp, lane);
        __syncthreads();
        convP<4, 4, 72, 35, 1, MB>(bufA, A_S, bufB, 36, B_S,
                                   g_Wp + 2056, ln2w, ln2b, warp, lane);
        __syncthreads();
        convP<4, 4, 36, 17, 1, MB>(bufB, B_S, bufA, 20, C_S,
                                   g_Wp + 2072, ln3w, ln3b, warp, lane);
        __syncthreads();
        convP<4, 4, 20,  8, 1, MB>(bufA, C_S, bufB, 8, D_S,
                                   g_Wp + 2088, ln4w, ln4b, warp, lane);
        __syncthreads();
        int cbase = 56 + (stream - 2) * 4;             // 56 or 60
        size_t obase = (size_t)b * 4096 + (size_t)cbase * 64;
        for (int t = tid; t < MB * 32; t += NT) {
            int s = t >> 5; int q = t & 31;
            int c = q >> 3, j = q & 7;
            out[obase + (size_t)c * 64 + (size_t)(mbase + s) * 8 + j] = bufB[s * D_S + c * 8 + j];
        }
    }
}

extern "C" void kernel_launch(void* const* d_in, const int* in_sizes, int n_in,
                              void* d_out, int out_size)
{
    const float* x   = (const float*)d_in[0];
    const float* w1  = (const float*)d_in[1];
    const float* w2  = (const float*)d_in[2];
    const float* w3  = (const float*)d_in[3];
    const float* w4  = (const float*)d_in[4];
    const float* f1  = (const float*)d_in[5];
    const float* f2  = (const float*)d_in[6];
    const float* f3  = (const float*)d_in[7];
    const float* f4  = (const float*)d_in[8];
    const float* ln1w = (const float*)d_in[9];
    const float* ln1b = (const float*)d_in[10];
    const float* ln2w = (const float*)d_in[11];
    const float* ln2b = (const float*)d_in[12];
    const float* ln3w = (const float*)d_in[13];
    const float* ln3b = (const float*)d_in[14];
    const float* ln4w = (const float*)d_in[15];
    const float* ln4b = (const float*)d_in[16];
    float* out = (float*)d_out;

    int B = in_sizes[0] / (CHN * 64);   // 4096

    init_pack<<<1, 256>>>(w1, w2, w3, w4, f1, f2, f3, f4);
    spectral_kernel<<<B * 8, NT>>>(x, out,
                                   ln1w, ln1b, ln2w, ln2b,
                                   ln3w, ln3b, ln4w, ln4b);
}

// round 14
// speedup vs baseline: 1.0007x; 1.0007x over previous
#include <cuda_runtime.h>
#include <math.h>

#define CHN 143
#define NT  128

// Packed weights (float4 per (cout,cin) triple, 4th lane = 0) + twiddles.
// Layout (float4 units): W1@0(32), W2@32(448), W3@480(784), W4@1264(784),
//                        F1@2048(8), F2@2056(16), F3@2072(16), F4@2088(16)
__device__ float4 g_Wp[2104];
__device__ float2 g_tw[144];

__device__ __forceinline__ void copy3(float* dst, const float* src) {
    dst[0] = src[0]; dst[1] = src[1]; dst[2] = src[2]; dst[3] = 0.f;
}

__global__ void init_pack(const float* w1, const float* w2, const float* w3, const float* w4,
                          const float* f1, const float* f2, const float* f3, const float* f4)
{
    int tid = threadIdx.x;
    float* g = (float*)g_Wp;
    for (int e = tid; e < 32;  e += 256) copy3(g + (0    + e) * 4, w1 + e * 3);
    for (int e = tid; e < 448; e += 256) copy3(g + (32   + e) * 4, w2 + e * 3);
    for (int e = tid; e < 784; e += 256) copy3(g + (480  + e) * 4, w3 + e * 3);
    for (int e = tid; e < 784; e += 256) copy3(g + (1264 + e) * 4, w4 + e * 3);
    for (int e = tid; e < 8;   e += 256) copy3(g + (2048 + e) * 4, f1 + e * 3);
    for (int e = tid; e < 16;  e += 256) copy3(g + (2056 + e) * 4, f2 + e * 3);
    for (int e = tid; e < 16;  e += 256) copy3(g + (2072 + e) * 4, f3 + e * 3);
    for (int e = tid; e < 16;  e += 256) copy3(g + (2088 + e) * 4, f4 + e * 3);
    if (tid < 143) {
        double a = -2.0 * 3.14159265358979323846 * (double)tid / 143.0;
        g_tw[tid] = make_float2((float)cos(a), (float)sin(a));
    }
}

// One DFT bin task via smem twiddle table: u in [0,144) -> (vector c, bin k).
// Independent FMAs per iteration; loop-carried dep is only the 2-cycle index
// recurrence, so the LDS latency pipelines. Writes |X[k]| and |X[143-k]|.
__device__ __forceinline__ void dft_one(int u, const float* rawp, const float2* twl, float* vinp)
{
    int c = (u >= 72) ? 1 : 0;
    int k = u - 72 * c;
    const float* v = rawp + c * 144;
    float re = 0.f, im = 0.f;
    unsigned mc = 0;
#pragma unroll 13
    for (int n = 0; n < 143; n++) {
        float2 w = twl[mc];
        float val = v[n];
        re = fmaf(w.x, val, re);
        im = fmaf(w.y, val, im);
        mc += (unsigned)k;
        mc = min(mc, mc - 143u);   // conditional wrap via unsigned-min trick
    }
    float mag = sqrtf(fmaf(re, re, im * im));
    vinp[c * 144 + k] = mag;
    if (k) vinp[c * 144 + 143 - k] = mag;
}

// Conv1d(k=3,s=2,VALID) + LayerNorm + ReLU, pair-of-outputs layout.
// Lane owns output pairs (2P, 2P+1), P = lane + 32p. One LDS.128 gives
// row[4P..4P+3]; the straddle element row[4P+4] comes from the next lane's
// .x via shuffle. Warp w owns channels c = w + 4r. Weights amortized over M.
// RowStride must be a multiple of 4 floats; padding garbage only reaches
// masked outputs (excluded from LN sums, never stored).
template<int Cin, int Cout, int RowStride, int Lout, int NP, int M>
__device__ __forceinline__ void convP(
    const float* __restrict__ in, int inStride,
    float* __restrict__ out, int outRow, int outStride,
    const float4* __restrict__ Wp,
    const float* __restrict__ gam, const float* __restrict__ bet,
    int warp, int lane)
{
    constexpr int ROWS  = Cout / 4;
    constexpr int LOADP = RowStride / 4;
    float a0[ROWS][M][NP], a1[ROWS][M][NP];
#pragma unroll
    for (int r = 0; r < ROWS; r++)
#pragma unroll
        for (int m = 0; m < M; m++)
#pragma unroll
            for (int p = 0; p < NP; p++) { a0[r][m][p] = 0.f; a1[r][m][p] = 0.f; }

#pragma unroll 2
    for (int ic = 0; ic < Cin; ic++) {
        float4 v[M][NP]; float ev[M][NP];
#pragma unroll
        for (int m = 0; m < M; m++) {
            const float* row = in + m * inStride + ic * RowStride;
#pragma unroll
            for (int p = 0; p < NP; p++) {
                int P = lane + 32 * p;
                v[m][p] = (P < LOADP) ? *(const float4*)(row + 4 * P)
                                      : make_float4(0.f, 0.f, 0.f, 0.f);
            }
        }
#pragma unroll
        for (int m = 0; m < M; m++)
#pragma unroll
            for (int p = 0; p < NP; p++) {
                float dn = __shfl_down_sync(0xffffffffu, v[m][p].x, 1);
                if (NP > 1) {
                    float nx = __shfl_sync(0xffffffffu,
                                           (p + 1 < NP) ? v[m][p + 1].x : 0.f, 0);
                    ev[m][p] = (lane == 31) ? nx : dn;
                } else {
                    ev[m][p] = dn;
                }
            }
#pragma unroll
        for (int r = 0; r < ROWS; r++) {
            int c = warp + 4 * r;
            float4 w = __ldg(Wp + c * Cin + ic);
#pragma unroll
            for (int m = 0; m < M; m++)
#pragma unroll
                for (int p = 0; p < NP; p++) {
                    a0[r][m][p] = fmaf(w.x, v[m][p].x, a0[r][m][p]);
                    a0[r][m][p] = fmaf(w.y, v[m][p].y, a0[r][m][p]);
                    a0[r][m][p] = fmaf(w.z, v[m][p].z, a0[r][m][p]);
                    a1[r][m][p] = fmaf(w.x, v[m][p].z, a1[r][m][p]);
                    a1[r][m][p] = fmaf(w.y, v[m][p].w, a1[r][m][p]);
                    a1[r][m][p] = fmaf(w.z, ev[m][p],  a1[r][m][p]);
                }
        }
    }

    float g0[NP], g1[NP], b0[NP], b1[NP];
#pragma unroll
    for (int p = 0; p < NP; p++) {
        int l = 2 * (lane + 32 * p);
        g0[p] = (l     < Lout) ? __ldg(gam + l)     : 0.f;
        b0[p] = (l     < Lout) ? __ldg(bet + l)     : 0.f;
        g1[p] = (l + 1 < Lout) ? __ldg(gam + l + 1) : 0.f;
        b1[p] = (l + 1 < Lout) ? __ldg(bet + l + 1) : 0.f;
    }
    const float invL = 1.0f / (float)Lout;

#pragma unroll
    for (int r = 0; r < ROWS; r++) {
        int c = warp + 4 * r;
#pragma unroll
        for (int m = 0; m < M; m++) {
            float s = 0.f;
#pragma unroll
            for (int p = 0; p < NP; p++) {
                int l = 2 * (lane + 32 * p);
                if (l     < Lout) s += a0[r][m][p];
                if (l + 1 < Lout) s += a1[r][m][p];
            }
#pragma unroll
            for (int o = 16; o; o >>= 1) s += __shfl_xor_sync(0xffffffffu, s, o);
            float mu = s * invL;

            float s2 = 0.f;
#pragma unroll
            for (int p = 0; p < NP; p++) {
                int l = 2 * (lane + 32 * p);
                if (l < Lout)     { float d = a0[r][m][p] - mu; s2 = fmaf(d, d, s2); }
                if (l + 1 < Lout) { float d = a1[r][m][p] - mu; s2 = fmaf(d, d, s2); }
            }
#pragma unroll
            for (int o = 16; o; o >>= 1) s2 += __shfl_xor_sync(0xffffffffu, s2, o);
            float inv = rsqrtf(fmaf(s2, invL, 1e-5f));

            float* orow = out + m * outStride + c * outRow;
#pragma unroll
            for (int p = 0; p < NP; p++) {
                int P = lane + 32 * p;
                int l = 2 * P;
                float o0 = fmaxf(fmaf((a0[r][m][p] - mu) * inv, g0[p], b0[p]), 0.f);
                float o1 = fmaxf(fmaf((a1[r][m][p] - mu) * inv, g1[p], b1[p]), 0.f);
                if (l + 1 < Lout) {
                    float2 t; t.x = o0; t.y = o1;
                    *(float2*)(orow + l) = t;
                } else if (l < Lout) {
                    orow[l] = o0;
                }
            }
        }
    }
}

// Block = (b, stream, m-half): processes MB=4 samples.
#define MB 4
#define RAW_S 288    // per-sample raw stride (2 x 144)
#define A_S   1152   // 16*72 stage-1 output
#define B_S   1008   // 28*36 stage-2 output
#define C_S   560    // 28*20 stage-3 output (rows padded 18->20)
#define D_S   224    // 28*8  stage-4 output

__global__ void __launch_bounds__(NT, 5)
spectral_kernel(const float* __restrict__ x, float* __restrict__ out,
                const float* __restrict__ ln1w, const float* __restrict__ ln1b,
                const float* __restrict__ ln2w, const float* __restrict__ ln2b,
                const float* __restrict__ ln3w, const float* __restrict__ ln3b,
                const float* __restrict__ ln4w, const float* __restrict__ ln4b)
{
    __shared__ __align__(16) float  bufA[MB * A_S];   // 18432 B
    __shared__ __align__(16) float  bufB[MB * B_S];   // 16128 B
    __shared__ __align__(16) float2 twl[144];         // 1152 B
    // raw/vin alias into bufB: both dead before stage 2 writes bufB.
    float* raw_s = bufB;               // MB * 288 floats
    float* vin_s = bufB + MB * RAW_S;  // MB * 288 floats (total 2304 <= 4032)

    int tid  = threadIdx.x;
    int lane = tid & 31, warp = tid >> 5;
    unsigned blk = blockIdx.x;
    int b      = (int)(blk >> 3);
    int rem    = (int)(blk & 7);
    int stream = rem >> 1;         // 0=cr, 1=cc, 2=cr_fft, 3=cc_fft
    int mbase  = (rem & 1) * MB;   // 0 or 4
    bool isfft = (stream >= 2);
    bool isrow = (stream == 0 || stream == 2);

    const float* xb = x + (size_t)b * (CHN * 64);

    // ---- gather MB (2,143) samples into smem ----
    // cr/cr_fft: sample m -> h = 3 + (m>>2), channels w = 2*(m&3) + c
    // cc/cc_fft: sample m -> h = m,          channels w = 3 + c
    for (int t = tid; t < MB * 286; t += NT) {
        int s = t / 286; int q = t - s * 286;
        int c = (q >= 143); int ch = q - 143 * c;
        int m = mbase + s;
        int base = isrow ? ((3 + (m >> 2)) * 8 + (m & 3) * 2)
                         : (m * 8 + 3);
        raw_s[s * RAW_S + c * 144 + ch] = __ldg(xb + ch * 64 + base + c);
    }
    if (isfft) {
        for (int t = tid; t < 143; t += NT) twl[t] = g_tw[t];
    }
    __syncthreads();

    // ---- DFT magnitude (fft streams only) ----
    if (isfft) {
        for (int t = tid; t < MB * 144; t += NT) {
            int s = t / 144; int u = t - s * 144;
            dft_one(u, raw_s + s * RAW_S, twl, vin_s + s * RAW_S);
        }
        __syncthreads();
    }

    const float* cin = isfft ? vin_s : raw_s;

    if (!isfft) {
        // stage 1 per-sample (weights tiny; keeps register peak low)
#pragma unroll
        for (int s = 0; s < MB; s++)
            convP<2, 16, 144, 71, 2, 1>(cin + s * RAW_S, RAW_S,
                                        bufA + s * A_S, 72, A_S,
                                        g_Wp + 0, ln1w, ln1b, warp, lane);
        __syncthreads();
        convP<16, 28, 72, 35, 1, MB>(bufA, A_S, bufB, 36, B_S,
                                     g_Wp + 32,   ln2w, ln2b, warp, lane);
        __syncthreads();
        convP<28, 28, 36, 17, 1, MB>(bufB, B_S, bufA, 20, C_S,
                                     g_Wp + 480,  ln3w, ln3b, warp, lane);
        __syncthreads();
        convP<28, 28, 20,  8, 1, MB>(bufA, C_S, bufB, 8, D_S,
                                     g_Wp + 1264, ln4w, ln4b, warp, lane);
        __syncthreads();
        int cbase = stream * 28;                       // 0 or 28
        size_t obase = (size_t)b * 4096 + (size_t)cbase * 64;
        for (int t = tid; t < MB * 224; t += NT) {
            int s = t / 224; int q = t - s * 224;
            int c = q >> 3, j = q & 7;
            out[obase + (size_t)c * 64 + (size_t)(mbase + s) * 8 + j] = bufB[s * D_S + q];
        }
    } else {
#pragma unroll
        for (int s = 0; s < MB; s++)
            convP<2, 4, 144, 71, 2, 1>(cin + s * RAW_S, RAW_S,
                                       bufA + s * A_S, 72, A_S,
                                       g_Wp + 2048, ln1w, ln1b, warp, lane);
        __syncthreads();
        convP<4, 4, 72, 35, 1, MB>(bufA, A_S, bufB, 36, B_S,
                                   g_Wp + 2056, ln2w, ln2b, warp, lane);
        __syncthreads();
        convP<4, 4, 36, 17, 1, MB>(bufB, B_S, bufA, 20, C_S,
                                   g_Wp + 2072, ln3w, ln3b, warp, lane);
        __syncthreads();
        convP<4, 4, 20,  8, 1, MB>(bufA, C_S, bufB, 8, D_S,
                                   g_Wp + 2088, ln4w, ln4b, warp, lane);
        __syncthreads();
        int cbase = 56 + (stream - 2) * 4;             // 56 or 60
        size_t obase = (size_t)b * 4096 + (size_t)cbase * 64;
        for (int t = tid; t < MB * 32; t += NT) {
            int s = t >> 5; int q = t & 31;
            int c = q >> 3, j = q & 7;
            out[obase + (size_t)c * 64 + (size_t)(mbase + s) * 8 + j] = bufB[s * D_S + c * 8 + j];
        }
    }
}

extern "C" void kernel_launch(void* const* d_in, const int* in_sizes, int n_in,
                              void* d_out, int out_size)
{
    const float* x   = (const float*)d_in[0];
    const float* w1  = (const float*)d_in[1];
    const float* w2  = (const float*)d_in[2];
    const float* w3  = (const float*)d_in[3];
    const float* w4  = (const float*)d_in[4];
    const float* f1  = (const float*)d_in[5];
    const float* f2  = (const float*)d_in[6];
    const float* f3  = (const float*)d_in[7];
    const float* f4  = (const float*)d_in[8];
    const float* ln1w = (const float*)d_in[9];
    const float* ln1b = (const float*)d_in[10];
    const float* ln2w = (const float*)d_in[11];
    const float* ln2b = (const float*)d_in[12];
    const float* ln3w = (const float*)d_in[13];
    const float* ln3b = (const float*)d_in[14];
    const float* ln4w = (const float*)d_in[15];
    const float* ln4b = (const float*)d_in[16];
    float* out = (float*)d_out;

    int B = in_sizes[0] / (CHN * 64);   // 4096

    init_pack<<<1, 256>>>(w1, w2, w3, w4, f1, f2, f3, f4);
    spectral_kernel<<<B * 8, NT>>>(x, out,
                                   ln1w, ln1b, ln2w, ln2b,
                                   ln3w, ln3b, ln4w, ln4b);
}

// round 15
// speedup vs baseline: 1.4075x; 1.4065x over previous
#include <cuda_runtime.h>
#include <math.h>

#define CHN 143
#define NT  128

// Packed weights (float4 per (cout,cin) triple, 4th lane = 0) + twiddles.
// Layout (float4 units): W1@0(32), W2@32(448), W3@480(784), W4@1264(784),
//                        F1@2048(8), F2@2056(16), F3@2072(16), F4@2088(16)
__device__ float4 g_Wp[2104];
__device__ float2 g_tw[144];

__device__ __forceinline__ void copy3(float* dst, const float* src) {
    dst[0] = src[0]; dst[1] = src[1]; dst[2] = src[2]; dst[3] = 0.f;
}

__global__ void init_pack(const float* w1, const float* w2, const float* w3, const float* w4,
                          const float* f1, const float* f2, const float* f3, const float* f4)
{
    int tid = threadIdx.x;
    float* g = (float*)g_Wp;
    for (int e = tid; e < 32;  e += 256) copy3(g + (0    + e) * 4, w1 + e * 3);
    for (int e = tid; e < 448; e += 256) copy3(g + (32   + e) * 4, w2 + e * 3);
    for (int e = tid; e < 784; e += 256) copy3(g + (480  + e) * 4, w3 + e * 3);
    for (int e = tid; e < 784; e += 256) copy3(g + (1264 + e) * 4, w4 + e * 3);
    for (int e = tid; e < 8;   e += 256) copy3(g + (2048 + e) * 4, f1 + e * 3);
    for (int e = tid; e < 16;  e += 256) copy3(g + (2056 + e) * 4, f2 + e * 3);
    for (int e = tid; e < 16;  e += 256) copy3(g + (2072 + e) * 4, f3 + e * 3);
    for (int e = tid; e < 16;  e += 256) copy3(g + (2088 + e) * 4, f4 + e * 3);
    if (tid < 143) {
        double a = -2.0 * 3.14159265358979323846 * (double)tid / 143.0;
        g_tw[tid] = make_float2((float)cos(a), (float)sin(a));
    }
}

// Pair-of-outputs conv (stages 1-2, Lout > 32): lane owns outputs (2P, 2P+1),
// P = lane + 32p. One LDS.128 gives row[4P..4P+3]; straddle element via shuffle.
// RowStride must be a multiple of 4 floats.
template<int Cin, int Cout, int RowStride, int Lout, int NP, int M>
__device__ __forceinline__ void convP(
    const float* __restrict__ in, int inStride,
    float* __restrict__ out, int outRow, int outStride,
    const float4* __restrict__ Wp,
    const float* __restrict__ gam, const float* __restrict__ bet,
    int warp, int lane)
{
    constexpr int ROWS  = Cout / 4;
    constexpr int LOADP = RowStride / 4;
    float a0[ROWS][M][NP], a1[ROWS][M][NP];
#pragma unroll
    for (int r = 0; r < ROWS; r++)
#pragma unroll
        for (int m = 0; m < M; m++)
#pragma unroll
            for (int p = 0; p < NP; p++) { a0[r][m][p] = 0.f; a1[r][m][p] = 0.f; }

#pragma unroll 2
    for (int ic = 0; ic < Cin; ic++) {
        float4 v[M][NP]; float ev[M][NP];
#pragma unroll
        for (int m = 0; m < M; m++) {
            const float* row = in + m * inStride + ic * RowStride;
#pragma unroll
            for (int p = 0; p < NP; p++) {
                int P = lane + 32 * p;
                v[m][p] = (P < LOADP) ? *(const float4*)(row + 4 * P)
                                      : make_float4(0.f, 0.f, 0.f, 0.f);
            }
        }
#pragma unroll
        for (int m = 0; m < M; m++)
#pragma unroll
            for (int p = 0; p < NP; p++) {
                float dn = __shfl_down_sync(0xffffffffu, v[m][p].x, 1);
                if (NP > 1) {
                    float nx = __shfl_sync(0xffffffffu,
                                           (p + 1 < NP) ? v[m][p + 1].x : 0.f, 0);
                    ev[m][p] = (lane == 31) ? nx : dn;
                } else {
                    ev[m][p] = dn;
                }
            }
#pragma unroll
        for (int r = 0; r < ROWS; r++) {
            int c = warp + 4 * r;
            float4 w = __ldg(Wp + c * Cin + ic);
#pragma unroll
            for (int m = 0; m < M; m++)
#pragma unroll
                for (int p = 0; p < NP; p++) {
                    a0[r][m][p] = fmaf(w.x, v[m][p].x, a0[r][m][p]);
                    a0[r][m][p] = fmaf(w.y, v[m][p].y, a0[r][m][p]);
                    a0[r][m][p] = fmaf(w.z, v[m][p].z, a0[r][m][p]);
                    a1[r][m][p] = fmaf(w.x, v[m][p].z, a1[r][m][p]);
                    a1[r][m][p] = fmaf(w.y, v[m][p].w, a1[r][m][p]);
                    a1[r][m][p] = fmaf(w.z, ev[m][p],  a1[r][m][p]);
                }
        }
    }

    float g0[NP], g1[NP], b0[NP], b1[NP];
#pragma unroll
    for (int p = 0; p < NP; p++) {
        int l = 2 * (lane + 32 * p);
        g0[p] = (l     < Lout) ? __ldg(gam + l)     : 0.f;
        b0[p] = (l     < Lout) ? __ldg(bet + l)     : 0.f;
        g1[p] = (l + 1 < Lout) ? __ldg(gam + l + 1) : 0.f;
        b1[p] = (l + 1 < Lout) ? __ldg(bet + l + 1) : 0.f;
    }
    const float invL = 1.0f / (float)Lout;

#pragma unroll
    for (int r = 0; r < ROWS; r++) {
        int c = warp + 4 * r;
#pragma unroll
        for (int m = 0; m < M; m++) {
            float s = 0.f;
#pragma unroll
            for (int p = 0; p < NP; p++) {
                int l = 2 * (lane + 32 * p);
                if (l     < Lout) s += a0[r][m][p];
                if (l + 1 < Lout) s += a1[r][m][p];
            }
#pragma unroll
            for (int o = 16; o; o >>= 1) s += __shfl_xor_sync(0xffffffffu, s, o);
            float mu = s * invL;

            float s2 = 0.f;
#pragma unroll
            for (int p = 0; p < NP; p++) {
                int l = 2 * (lane + 32 * p);
                if (l < Lout)     { float d = a0[r][m][p] - mu; s2 = fmaf(d, d, s2); }
                if (l + 1 < Lout) { float d = a1[r][m][p] - mu; s2 = fmaf(d, d, s2); }
            }
#pragma unroll
            for (int o = 16; o; o >>= 1) s2 += __shfl_xor_sync(0xffffffffu, s2, o);
            float inv = rsqrtf(fmaf(s2, invL, 1e-5f));

            float* orow = out + m * outStride + c * outRow;
#pragma unroll
            for (int p = 0; p < NP; p++) {
                int P = lane + 32 * p;
                int l = 2 * P;
                float o0 = fmaxf(fmaf((a0[r][m][p] - mu) * inv, g0[p], b0[p]), 0.f);
                float o1 = fmaxf(fmaf((a1[r][m][p] - mu) * inv, g1[p], b1[p]), 0.f);
                if (l + 1 < Lout) {
                    float2 t; t.x = o0; t.y = o1;
                    *(float2*)(orow + l) = t;
                } else if (l < Lout) {
                    orow[l] = o0;
                }
            }
        }
    }
}

// Single-output-per-lane conv (stages 3-4, Lout <= 32): 3 FMAs per (r,m),
// guarded float2+scalar loads. Weights amortized over M samples.
template<int Cin, int Cout, int Sin, int Lout, int M>
__device__ __forceinline__ void convS(
    const float* __restrict__ in, int inStride,
    float* __restrict__ out, int Sout, int outStride,
    const float4* __restrict__ Wp,
    const float* __restrict__ gam, const float* __restrict__ bet,
    int warp, int lane)
{
    constexpr int ROWS = Cout / 4;
    float acc[ROWS][M];
#pragma unroll
    for (int r = 0; r < ROWS; r++)
#pragma unroll
        for (int m = 0; m < M; m++) acc[r][m] = 0.f;

#pragma unroll 2
    for (int ic = 0; ic < Cin; ic++) {
        float x0[M], x1[M], x2[M];
#pragma unroll
        for (int m = 0; m < M; m++) {
            const float* row = in + m * inStride + ic * Sin;
            if (lane < Lout) {
                float2 p = *(const float2*)(row + 2 * lane);
                x0[m] = p.x; x1[m] = p.y; x2[m] = row[2 * lane + 2];
            } else { x0[m] = 0.f; x1[m] = 0.f; x2[m] = 0.f; }
        }
#pragma unroll
        for (int r = 0; r < ROWS; r++) {
            int c = warp + 4 * r;
            float4 w = __ldg(Wp + c * Cin + ic);
#pragma unroll
            for (int m = 0; m < M; m++) {
                acc[r][m] = fmaf(w.x, x0[m], acc[r][m]);
                acc[r][m] = fmaf(w.y, x1[m], acc[r][m]);
                acc[r][m] = fmaf(w.z, x2[m], acc[r][m]);
            }
        }
    }

    float gv = (lane < Lout) ? __ldg(gam + lane) : 0.f;
    float bv = (lane < Lout) ? __ldg(bet + lane) : 0.f;
    const float invL = 1.0f / (float)Lout;

#pragma unroll
    for (int r = 0; r < ROWS; r++) {
        int c = warp + 4 * r;
#pragma unroll
        for (int m = 0; m < M; m++) {
            float s = (lane < Lout) ? acc[r][m] : 0.f;
#pragma unroll
            for (int o = 16; o; o >>= 1) s += __shfl_xor_sync(0xffffffffu, s, o);
            float mu = s * invL;

            float s2 = 0.f;
            if (lane < Lout) { float d = acc[r][m] - mu; s2 = d * d; }
#pragma unroll
            for (int o = 16; o; o >>= 1) s2 += __shfl_xor_sync(0xffffffffu, s2, o);
            float inv = rsqrtf(fmaf(s2, invL, 1e-5f));

            if (lane < Lout) {
                float val = (acc[r][m] - mu) * inv;
                out[m * outStride + c * Sout + lane] = fmaxf(fmaf(val, gv, bv), 0.f);
            }
        }
    }
}

// Block = (b, stream, m-half): processes MB=4 samples.
#define MB 4
#define RAW_S 288    // per-sample raw/fold/vin stride (2 x 144)
#define A_S   1152   // 16*72 stage-1 output
#define B_S   1008   // 28*36 stage-2 output
#define C_S   504    // 28*18 stage-3 output
#define D_S   224    // 28*8  stage-4 output

__global__ void __launch_bounds__(NT, 5)
spectral_kernel(const float* __restrict__ x, float* __restrict__ out,
                const float* __restrict__ ln1w, const float* __restrict__ ln1b,
                const float* __restrict__ ln2w, const float* __restrict__ ln2b,
                const float* __restrict__ ln3w, const float* __restrict__ ln3b,
                const float* __restrict__ ln4w, const float* __restrict__ ln4b)
{
    __shared__ __align__(16) float  bufA[MB * A_S];   // 18432 B
    __shared__ __align__(16) float  bufB[MB * B_S];   // 16128 B
    __shared__ __align__(16) float2 twl[144];         // 1152 B
    // raw/vin/fold alias into bufB: all dead before stage 2 writes bufB.
    float* raw_s  = bufB;                   // MB*288 floats [0,1152)
    float* vin_s  = bufB + MB * RAW_S;      // MB*288 floats [1152,2304)
    float* fold_s = bufB + 2 * MB * RAW_S;  // MB*288 floats [2304,3456) <= 4032

    int tid  = threadIdx.x;
    int lane = tid & 31, warp = tid >> 5;
    unsigned blk = blockIdx.x;
    int b      = (int)(blk >> 3);
    int rem    = (int)(blk & 7);
    int stream = rem >> 1;         // 0=cr, 1=cc, 2=cr_fft, 3=cc_fft
    int mbase  = (rem & 1) * MB;   // 0 or 4
    bool isfft = (stream >= 2);
    bool isrow = (stream == 0 || stream == 2);

    const float* xb = x + (size_t)b * (CHN * 64);

    // ---- gather MB (2,143) samples into smem ----
    // cr/cr_fft: sample m -> h = 3 + (m>>2), channels w = 2*(m&3) + c
    // cc/cc_fft: sample m -> h = m,          channels w = 3 + c
    for (int t = tid; t < MB * 286; t += NT) {
        int s = t / 286; int q = t - s * 286;
        int c = (q >= 143); int ch = q - 143 * c;
        int m = mbase + s;
        int base = isrow ? ((3 + (m >> 2)) * 8 + (m & 3) * 2)
                         : (m * 8 + 3);
        raw_s[s * RAW_S + c * 144 + ch] = __ldg(xb + ch * 64 + base + c);
    }
    if (isfft) {
        for (int t = tid; t < 143; t += NT) twl[t] = g_tw[t];
    }
    __syncthreads();

    // ---- DFT magnitude via real-input folding (fft streams only) ----
    // X[k] = x0 + sum_{n=1..71} (x[n]+x[143-n])cos - i(x[n]-x[143-n])sin.
    if (isfft) {
        // build (sum, diff) float2 table per vector
        for (int t = tid; t < MB * 142; t += NT) {
            int s = t / 142; int q = t - s * 142;
            int c = (q >= 71); int n = q - 71 * c + 1;   // 1..71
            const float* v = raw_s + s * RAW_S + c * 144;
            float a = v[n], d = v[143 - n];
            ((float2*)(fold_s + s * RAW_S + c * 144))[n] = make_float2(a + d, a - d);
        }
        __syncthreads();
        for (int t = tid; t < MB * 144; t += NT) {
            int s = t / 144; int u = t - s * 144;
            int c = (u >= 72); int k = u - 72 * c;
            const float2* f = (const float2*)(fold_s + s * RAW_S + c * 144);
            float re = raw_s[s * RAW_S + c * 144];   // x[0]
            float im = 0.f;
            unsigned mc = 0;
#pragma unroll 7
            for (int n = 1; n <= 71; n++) {
                mc += (unsigned)k;
                mc = min(mc, mc - 143u);
                float2 w  = twl[mc];
                float2 sd = f[n];
                re = fmaf(w.x, sd.x, re);
                im = fmaf(w.y, sd.y, im);
            }
            float mag = sqrtf(fmaf(re, re, im * im));
            float* vp = vin_s + s * RAW_S + c * 144;
            vp[k] = mag;
            if (k) vp[143 - k] = mag;
        }
        __syncthreads();
    }

    const float* cin = isfft ? vin_s : raw_s;

    if (!isfft) {
#pragma unroll
        for (int s = 0; s < MB; s++)
            convP<2, 16, 144, 71, 2, 1>(cin + s * RAW_S, RAW_S,
                                        bufA + s * A_S, 72, A_S,
                                        g_Wp + 0, ln1w, ln1b, warp, lane);
        __syncthreads();
        convP<16, 28, 72, 35, 1, MB>(bufA, A_S, bufB, 36, B_S,
                                     g_Wp + 32,   ln2w, ln2b, warp, lane);
        __syncthreads();
        convS<28, 28, 36, 17, MB>(bufB, B_S, bufA, 18, C_S,
                                  g_Wp + 480,  ln3w, ln3b, warp, lane);
        __syncthreads();
        convS<28, 28, 18,  8, MB>(bufA, C_S, bufB, 8, D_S,
                                  g_Wp + 1264, ln4w, ln4b, warp, lane);
        __syncthreads();
        int cbase = stream * 28;                       // 0 or 28
        size_t obase = (size_t)b * 4096 + (size_t)cbase * 64;
        for (int t = tid; t < MB * 224; t += NT) {
            int s = t / 224; int q = t - s * 224;
            int c = q >> 3, j = q & 7;
            out[obase + (size_t)c * 64 + (size_t)(mbase + s) * 8 + j] = bufB[s * D_S + q];
        }
    } else {
#pragma unroll
        for (int s = 0; s < MB; s++)
            convP<2, 4, 144, 71, 2, 1>(cin + s * RAW_S, RAW_S,
                                       bufA + s * A_S, 72, A_S,
                                       g_Wp + 2048, ln1w, ln1b, warp, lane);
        __syncthreads();
        convP<4, 4, 72, 35, 1, MB>(bufA, A_S, bufB, 36, B_S,
                                   g_Wp + 2056, ln2w, ln2b, warp, lane);
        __syncthreads();
        convS<4, 4, 36, 17, MB>(bufB, B_S, bufA, 18, C_S,
                                g_Wp + 2072, ln3w, ln3b, warp, lane);
        __syncthreads();
        convS<4, 4, 18,  8, MB>(bufA, C_S, bufB, 8, D_S,
                                g_Wp + 2088, ln4w, ln4b, warp, lane);
        __syncthreads();
        int cbase = 56 + (stream - 2) * 4;             // 56 or 60
        size_t obase = (size_t)b * 4096 + (size_t)cbase * 64;
        for (int t = tid; t < MB * 32; t += NT) {
            int s = t >> 5; int q = t & 31;
            int c = q >> 3, j = q & 7;
            out[obase + (size_t)c * 64 + (size_t)(mbase + s) * 8 + j] = bufB[s * D_S + c * 8 + j];
        }
    }
}

extern "C" void kernel_launch(void* const* d_in, const int* in_sizes, int n_in,
                              void* d_out, int out_size)
{
    const float* x   = (const float*)d_in[0];
    const float* w1  = (const float*)d_in[1];
    const float* w2  = (const float*)d_in[2];
    const float* w3  = (const float*)d_in[3];
    const float* w4  = (const float*)d_in[4];
    const float* f1  = (const float*)d_in[5];
    const float* f2  = (const float*)d_in[6];
    const float* f3  = (const float*)d_in[7];
    const float* f4  = (const float*)d_in[8];
    const float* ln1w = (const float*)d_in[9];
    const float* ln1b = (const float*)d_in[10];
    const float* ln2w = (const float*)d_in[11];
    const float* ln2b = (const float*)d_in[12];
    const float* ln3w = (const float*)d_in[13];
    const float* ln3b = (const float*)d_in[14];
    const float* ln4w = (const float*)d_in[15];
    const float* ln4b = (const float*)d_in[16];
    float* out = (float*)d_out;

    int B = in_sizes[0] / (CHN * 64);   // 4096

    init_pack<<<1, 256>>>(w1, w2, w3, w4, f1, f2, f3, f4);
    spectral_kernel<<<B * 8, NT>>>(x, out,
                                   ln1w, ln1b, ln2w, ln2b,
                                   ln3w, ln3b, ln4w, ln4b);
}

// round 16
// speedup vs baseline: 1.6418x; 1.1665x over previous
#include <cuda_runtime.h>
#include <math.h>

#define CHN 143
#define NT  128

// Packed weights (float4 per (cout,cin) triple, 4th lane = 0) + twiddles.
// Layout (float4 units): W1@0(32), W2@32(448), W3@480(784), W4@1264(784),
//                        F1@2048(8), F2@2056(16), F3@2072(16), F4@2088(16)
__device__ float4 g_Wp[2104];
__device__ float2 g_tw[144];

__device__ __forceinline__ void copy3(float* dst, const float* src) {
    dst[0] = src[0]; dst[1] = src[1]; dst[2] = src[2]; dst[3] = 0.f;
}

__global__ void init_pack(const float* w1, const float* w2, const float* w3, const float* w4,
                          const float* f1, const float* f2, const float* f3, const float* f4)
{
    int tid = threadIdx.x;
    float* g = (float*)g_Wp;
    for (int e = tid; e < 32;  e += 256) copy3(g + (0    + e) * 4, w1 + e * 3);
    for (int e = tid; e < 448; e += 256) copy3(g + (32   + e) * 4, w2 + e * 3);
    for (int e = tid; e < 784; e += 256) copy3(g + (480  + e) * 4, w3 + e * 3);
    for (int e = tid; e < 784; e += 256) copy3(g + (1264 + e) * 4, w4 + e * 3);
    for (int e = tid; e < 8;   e += 256) copy3(g + (2048 + e) * 4, f1 + e * 3);
    for (int e = tid; e < 16;  e += 256) copy3(g + (2056 + e) * 4, f2 + e * 3);
    for (int e = tid; e < 16;  e += 256) copy3(g + (2072 + e) * 4, f3 + e * 3);
    for (int e = tid; e < 16;  e += 256) copy3(g + (2088 + e) * 4, f4 + e * 3);
    if (tid < 143) {
        double a = -2.0 * 3.14159265358979323846 * (double)tid / 143.0;
        g_tw[tid] = make_float2((float)cos(a), (float)sin(a));
    }
}

// Pair-of-outputs conv (stages 1-2, Lout > 32): lane owns outputs (2P, 2P+1),
// P = lane + 32p. One LDS.128 gives row[4P..4P+3]; straddle element via shuffle.
// RowStride must be a multiple of 4 floats.
template<int Cin, int Cout, int RowStride, int Lout, int NP, int M>
__device__ __forceinline__ void convP(
    const float* __restrict__ in, int inStride,
    float* __restrict__ out, int outRow, int outStride,
    const float4* __restrict__ Wp,
    const float* __restrict__ gam, const float* __restrict__ bet,
    int warp, int lane)
{
    constexpr int ROWS  = Cout / 4;
    constexpr int LOADP = RowStride / 4;
    float a0[ROWS][M][NP], a1[ROWS][M][NP];
#pragma unroll
    for (int r = 0; r < ROWS; r++)
#pragma unroll
        for (int m = 0; m < M; m++)
#pragma unroll
            for (int p = 0; p < NP; p++) { a0[r][m][p] = 0.f; a1[r][m][p] = 0.f; }

#pragma unroll 2
    for (int ic = 0; ic < Cin; ic++) {
        float4 v[M][NP]; float ev[M][NP];
#pragma unroll
        for (int m = 0; m < M; m++) {
            const float* row = in + m * inStride + ic * RowStride;
#pragma unroll
            for (int p = 0; p < NP; p++) {
                int P = lane + 32 * p;
                v[m][p] = (P < LOADP) ? *(const float4*)(row + 4 * P)
                                      : make_float4(0.f, 0.f, 0.f, 0.f);
            }
        }
#pragma unroll
        for (int m = 0; m < M; m++)
#pragma unroll
            for (int p = 0; p < NP; p++) {
                float dn = __shfl_down_sync(0xffffffffu, v[m][p].x, 1);
                if (NP > 1) {
                    float nx = __shfl_sync(0xffffffffu,
                                           (p + 1 < NP) ? v[m][p + 1].x : 0.f, 0);
                    ev[m][p] = (lane == 31) ? nx : dn;
                } else {
                    ev[m][p] = dn;
                }
            }
#pragma unroll
        for (int r = 0; r < ROWS; r++) {
            int c = warp + 4 * r;
            float4 w = __ldg(Wp + c * Cin + ic);
#pragma unroll
            for (int m = 0; m < M; m++)
#pragma unroll
                for (int p = 0; p < NP; p++) {
                    a0[r][m][p] = fmaf(w.x, v[m][p].x, a0[r][m][p]);
                    a0[r][m][p] = fmaf(w.y, v[m][p].y, a0[r][m][p]);
                    a0[r][m][p] = fmaf(w.z, v[m][p].z, a0[r][m][p]);
                    a1[r][m][p] = fmaf(w.x, v[m][p].z, a1[r][m][p]);
                    a1[r][m][p] = fmaf(w.y, v[m][p].w, a1[r][m][p]);
                    a1[r][m][p] = fmaf(w.z, ev[m][p],  a1[r][m][p]);
                }
        }
    }

    float g0[NP], g1[NP], b0[NP], b1[NP];
#pragma unroll
    for (int p = 0; p < NP; p++) {
        int l = 2 * (lane + 32 * p);
        g0[p] = (l     < Lout) ? __ldg(gam + l)     : 0.f;
        b0[p] = (l     < Lout) ? __ldg(bet + l)     : 0.f;
        g1[p] = (l + 1 < Lout) ? __ldg(gam + l + 1) : 0.f;
        b1[p] = (l + 1 < Lout) ? __ldg(bet + l + 1) : 0.f;
    }
    const float invL = 1.0f / (float)Lout;

#pragma unroll
    for (int r = 0; r < ROWS; r++) {
        int c = warp + 4 * r;
#pragma unroll
        for (int m = 0; m < M; m++) {
            float s = 0.f;
#pragma unroll
            for (int p = 0; p < NP; p++) {
                int l = 2 * (lane + 32 * p);
                if (l     < Lout) s += a0[r][m][p];
                if (l + 1 < Lout) s += a1[r][m][p];
            }
#pragma unroll
            for (int o = 16; o; o >>= 1) s += __shfl_xor_sync(0xffffffffu, s, o);
            float mu = s * invL;

            float s2 = 0.f;
#pragma unroll
            for (int p = 0; p < NP; p++) {
                int l = 2 * (lane + 32 * p);
                if (l < Lout)     { float d = a0[r][m][p] - mu; s2 = fmaf(d, d, s2); }
                if (l + 1 < Lout) { float d = a1[r][m][p] - mu; s2 = fmaf(d, d, s2); }
            }
#pragma unroll
            for (int o = 16; o; o >>= 1) s2 += __shfl_xor_sync(0xffffffffu, s2, o);
            float inv = rsqrtf(fmaf(s2, invL, 1e-5f));

            float* orow = out + m * outStride + c * outRow;
#pragma unroll
            for (int p = 0; p < NP; p++) {
                int P = lane + 32 * p;
                int l = 2 * P;
                float o0 = fmaxf(fmaf((a0[r][m][p] - mu) * inv, g0[p], b0[p]), 0.f);
                float o1 = fmaxf(fmaf((a1[r][m][p] - mu) * inv, g1[p], b1[p]), 0.f);
                if (l + 1 < Lout) {
                    float2 t; t.x = o0; t.y = o1;
                    *(float2*)(orow + l) = t;
                } else if (l < Lout) {
                    orow[l] = o0;
                }
            }
        }
    }
}

// Single-output-per-lane conv (stage 3, Lout <= 32): 3 FMAs per (r,m),
// guarded float2+scalar loads. Weights amortized over M samples.
template<int Cin, int Cout, int Sin, int Lout, int M>
__device__ __forceinline__ void convS(
    const float* __restrict__ in, int inStride,
    float* __restrict__ out, int Sout, int outStride,
    const float4* __restrict__ Wp,
    const float* __restrict__ gam, const float* __restrict__ bet,
    int warp, int lane)
{
    constexpr int ROWS = Cout / 4;
    float acc[ROWS][M];
#pragma unroll
    for (int r = 0; r < ROWS; r++)
#pragma unroll
        for (int m = 0; m < M; m++) acc[r][m] = 0.f;

#pragma unroll 2
    for (int ic = 0; ic < Cin; ic++) {
        float x0[M], x1[M], x2[M];
#pragma unroll
        for (int m = 0; m < M; m++) {
            const float* row = in + m * inStride + ic * Sin;
            if (lane < Lout) {
                float2 p = *(const float2*)(row + 2 * lane);
                x0[m] = p.x; x1[m] = p.y; x2[m] = row[2 * lane + 2];
            } else { x0[m] = 0.f; x1[m] = 0.f; x2[m] = 0.f; }
        }
#pragma unroll
        for (int r = 0; r < ROWS; r++) {
            int c = warp + 4 * r;
            float4 w = __ldg(Wp + c * Cin + ic);
#pragma unroll
            for (int m = 0; m < M; m++) {
                acc[r][m] = fmaf(w.x, x0[m], acc[r][m]);
                acc[r][m] = fmaf(w.y, x1[m], acc[r][m]);
                acc[r][m] = fmaf(w.z, x2[m], acc[r][m]);
            }
        }
    }

    float gv = (lane < Lout) ? __ldg(gam + lane) : 0.f;
    float bv = (lane < Lout) ? __ldg(bet + lane) : 0.f;
    const float invL = 1.0f / (float)Lout;

#pragma unroll
    for (int r = 0; r < ROWS; r++) {
        int c = warp + 4 * r;
#pragma unroll
        for (int m = 0; m < M; m++) {
            float s = (lane < Lout) ? acc[r][m] : 0.f;
#pragma unroll
            for (int o = 16; o; o >>= 1) s += __shfl_xor_sync(0xffffffffu, s, o);
            float mu = s * invL;

            float s2 = 0.f;
            if (lane < Lout) { float d = acc[r][m] - mu; s2 = d * d; }
#pragma unroll
            for (int o = 16; o; o >>= 1) s2 += __shfl_xor_sync(0xffffffffu, s2, o);
            float inv = rsqrtf(fmaf(s2, invL, 1e-5f));

            if (lane < Lout) {
                float val = (acc[r][m] - mu) * inv;
                out[m * outStride + c * Sout + lane] = fmaxf(fmaf(val, gv, bv), 0.f);
            }
        }
    }
}

// Stage-4 conv (Lout = 8): 4 samples packed into one warp. lane = s*8 + j.
// All 32 lanes productive; LN reduction over width-8 shuffle groups.
template<int Cin, int Cout, int Sin>
__device__ __forceinline__ void convS4(
    const float* __restrict__ in, int inStride,
    float* __restrict__ out, int Sout, int outStride,
    const float4* __restrict__ Wp,
    const float* __restrict__ gam, const float* __restrict__ bet,
    int warp, int lane)
{
    constexpr int ROWS = Cout / 4;
    int s4 = lane >> 3, j = lane & 7;
    const float* basep = in + s4 * inStride + 2 * j;
    float acc[ROWS];
#pragma unroll
    for (int r = 0; r < ROWS; r++) acc[r] = 0.f;

#pragma unroll 4
    for (int ic = 0; ic < Cin; ic++) {
        const float* row = basep + ic * Sin;
        float2 p = *(const float2*)row;   // elements 2j, 2j+1 (8B aligned)
        float x2 = row[2];                // element 2j+2 (max index 16 < Sin)
#pragma unroll
        for (int r = 0; r < ROWS; r++) {
            int c = warp + 4 * r;
            float4 w = __ldg(Wp + c * Cin + ic);
            acc[r] = fmaf(w.x, p.x, acc[r]);
            acc[r] = fmaf(w.y, p.y, acc[r]);
            acc[r] = fmaf(w.z, x2,  acc[r]);
        }
    }

    float gv = __ldg(gam + j);
    float bv = __ldg(bet + j);
    const float invL = 0.125f;

#pragma unroll
    for (int r = 0; r < ROWS; r++) {
        int c = warp + 4 * r;
        float s = acc[r];
#pragma unroll
        for (int o = 4; o; o >>= 1) s += __shfl_xor_sync(0xffffffffu, s, o);
        float mu = s * invL;

        float d = acc[r] - mu;
        float s2 = d * d;
#pragma unroll
        for (int o = 4; o; o >>= 1) s2 += __shfl_xor_sync(0xffffffffu, s2, o);
        float inv = rsqrtf(fmaf(s2, invL, 1e-5f));

        float val = (acc[r] - mu) * inv;
        out[s4 * outStride + c * Sout + j] = fmaxf(fmaf(val, gv, bv), 0.f);
    }
}

// Block = (b, stream, m-half): processes MB=4 samples.
#define MB 4
#define RAW_S 288    // per-sample raw/fold/vin stride (2 x 144)
#define A_S   1152   // 16*72 stage-1 output
#define B_S   1008   // 28*36 stage-2 output
#define C_S   504    // 28*18 stage-3 output
#define D_S   224    // 28*8  stage-4 output

__global__ void __launch_bounds__(NT, 5)
spectral_kernel(const float* __restrict__ x, float* __restrict__ out,
                const float* __restrict__ ln1w, const float* __restrict__ ln1b,
                const float* __restrict__ ln2w, const float* __restrict__ ln2b,
                const float* __restrict__ ln3w, const float* __restrict__ ln3b,
                const float* __restrict__ ln4w, const float* __restrict__ ln4b)
{
    __shared__ __align__(16) float  bufA[MB * A_S];   // 18432 B
    __shared__ __align__(16) float  bufB[MB * B_S];   // 16128 B
    __shared__ __align__(16) float2 twl[144];         // 1152 B
    // raw/vin/fold alias into bufB: all dead before stage 2 writes bufB.
    float* raw_s  = bufB;                   // MB*288 floats [0,1152)
    float* vin_s  = bufB + MB * RAW_S;      // MB*288 floats [1152,2304)
    float* fold_s = bufB + 2 * MB * RAW_S;  // MB*288 floats [2304,3456) <= 4032

    int tid  = threadIdx.x;
    int lane = tid & 31, warp = tid >> 5;
    unsigned blk = blockIdx.x;
    int b      = (int)(blk >> 3);
    int rem    = (int)(blk & 7);
    int stream = rem >> 1;         // 0=cr, 1=cc, 2=cr_fft, 3=cc_fft
    int mbase  = (rem & 1) * MB;   // 0 or 4
    bool isfft = (stream >= 2);
    bool isrow = (stream == 0 || stream == 2);

    const float* xb = x + (size_t)b * (CHN * 64);

    // ---- gather MB (2,143) samples into smem ----
    if (isrow) {
        // cr/cr_fft: the block's 4 samples (wp=0..3, c=0..1) are exactly the 8
        // consecutive floats x[b][ch][3+hh][0..7]: two LDG.128 per channel.
        int rowoff = (3 + (mbase >> 2)) * 8;
        for (int ch = tid; ch < 143; ch += NT) {
            const float* src = xb + ch * 64 + rowoff;
            float4 v0 = *(const float4*)(src);
            float4 v1 = *(const float4*)(src + 4);
            raw_s[0 * RAW_S +       ch] = v0.x;
            raw_s[0 * RAW_S + 144 + ch] = v0.y;
            raw_s[1 * RAW_S +       ch] = v0.z;
            raw_s[1 * RAW_S + 144 + ch] = v0.w;
            raw_s[2 * RAW_S +       ch] = v1.x;
            raw_s[2 * RAW_S + 144 + ch] = v1.y;
            raw_s[3 * RAW_S +       ch] = v1.z;
            raw_s[3 * RAW_S + 144 + ch] = v1.w;
        }
    } else {
        // cc/cc_fft: sample m -> h = m, channels w = 3 + c (scattered rows)
        for (int t = tid; t < MB * 286; t += NT) {
            int s = t / 286; int q = t - s * 286;
            int c = (q >= 143); int ch = q - 143 * c;
            int m = mbase + s;
            raw_s[s * RAW_S + c * 144 + ch] = __ldg(xb + ch * 64 + m * 8 + 3 + c);
        }
    }
    if (isfft) {
        for (int t = tid; t < 143; t += NT) twl[t] = g_tw[t];
    }
    __syncthreads();

    // ---- DFT magnitude via real-input folding (fft streams only) ----
    // X[k] = x0 + sum_{n=1..71} (x[n]+x[143-n])cos - i(x[n]-x[143-n])sin.
    if (isfft) {
        for (int t = tid; t < MB * 142; t += NT) {
            int s = t / 142; int q = t - s * 142;
            int c = (q >= 71); int n = q - 71 * c + 1;   // 1..71
            const float* v = raw_s + s * RAW_S + c * 144;
            float a = v[n], d = v[143 - n];
            ((float2*)(fold_s + s * RAW_S + c * 144))[n] = make_float2(a + d, a - d);
        }
        __syncthreads();
        for (int t = tid; t < MB * 144; t += NT) {
            int s = t / 144; int u = t - s * 144;
            int c = (u >= 72); int k = u - 72 * c;
            const float2* f = (const float2*)(fold_s + s * RAW_S + c * 144);
            float re = raw_s[s * RAW_S + c * 144];   // x[0]
            float im = 0.f;
            unsigned mc = 0;
#pragma unroll 7
            for (int n = 1; n <= 71; n++) {
                mc += (unsigned)k;
                mc = min(mc, mc - 143u);
                float2 w  = twl[mc];
                float2 sd = f[n];
                re = fmaf(w.x, sd.x, re);
                im = fmaf(w.y, sd.y, im);
            }
            float mag = sqrtf(fmaf(re, re, im * im));
            float* vp = vin_s + s * RAW_S + c * 144;
            vp[k] = mag;
            if (k) vp[143 - k] = mag;
        }
        __syncthreads();
    }

    const float* cin = isfft ? vin_s : raw_s;

    if (!isfft) {
#pragma unroll
        for (int s = 0; s < MB; s++)
            convP<2, 16, 144, 71, 2, 1>(cin + s * RAW_S, RAW_S,
                                        bufA + s * A_S, 72, A_S,
                                        g_Wp + 0, ln1w, ln1b, warp, lane);
        __syncthreads();
        convP<16, 28, 72, 35, 1, MB>(bufA, A_S, bufB, 36, B_S,
                                     g_Wp + 32,   ln2w, ln2b, warp, lane);
        __syncthreads();
        convS<28, 28, 36, 17, MB>(bufB, B_S, bufA, 18, C_S,
                                  g_Wp + 480,  ln3w, ln3b, warp, lane);
        __syncthreads();
        convS4<28, 28, 18>(bufA, C_S, bufB, 8, D_S,
                           g_Wp + 1264, ln4w, ln4b, warp, lane);
        __syncthreads();
        int cbase = stream * 28;                       // 0 or 28
        size_t obase = (size_t)b * 4096 + (size_t)cbase * 64;
        for (int t = tid; t < MB * 224; t += NT) {
            int s = t / 224; int q = t - s * 224;
            int c = q >> 3, j = q & 7;
            out[obase + (size_t)c * 64 + (size_t)(mbase + s) * 8 + j] = bufB[s * D_S + q];
        }
    } else {
#pragma unroll
        for (int s = 0; s < MB; s++)
            convP<2, 4, 144, 71, 2, 1>(cin + s * RAW_S, RAW_S,
                                       bufA + s * A_S, 72, A_S,
                                       g_Wp + 2048, ln1w, ln1b, warp, lane);
        __syncthreads();
        convP<4, 4, 72, 35, 1, MB>(bufA, A_S, bufB, 36, B_S,
                                   g_Wp + 2056, ln2w, ln2b, warp, lane);
        __syncthreads();
        convS<4, 4, 36, 17, MB>(bufB, B_S, bufA, 18, C_S,
                                g_Wp + 2072, ln3w, ln3b, warp, lane);
        __syncthreads();
        convS4<4, 4, 18>(bufA, C_S, bufB, 8, D_S,
                         g_Wp + 2088, ln4w, ln4b, warp, lane);
        __syncthreads();
        int cbase = 56 + (stream - 2) * 4;             // 56 or 60
        size_t obase = (size_t)b * 4096 + (size_t)cbase * 64;
        for (int t = tid; t < MB * 32; t += NT) {
            int s = t >> 5; int q = t & 31;
            int c = q >> 3, j = q & 7;
            out[obase + (size_t)c * 64 + (size_t)(mbase + s) * 8 + j] = bufB[s * D_S + c * 8 + j];
        }
    }
}

extern "C" void kernel_launch(void* const* d_in, const int* in_sizes, int n_in,
                              void* d_out, int out_size)
{
    const float* x   = (const float*)d_in[0];
    const float* w1  = (const float*)d_in[1];
    const float* w2  = (const float*)d_in[2];
    const float* w3  = (const float*)d_in[3];
    const float* w4  = (const float*)d_in[4];
    const float* f1  = (const float*)d_in[5];
    const float* f2  = (const float*)d_in[6];
    const float* f3  = (const float*)d_in[7];
    const float* f4  = (const float*)d_in[8];
    const float* ln1w = (const float*)d_in[9];
    const float* ln1b = (const float*)d_in[10];
    const float* ln2w = (const float*)d_in[11];
    const float* ln2b = (const float*)d_in[12];
    const float* ln3w = (const float*)d_in[13];
    const float* ln3b = (const float*)d_in[14];
    const float* ln4w = (const float*)d_in[15];
    const float* ln4b = (const float*)d_in[16];
    float* out = (float*)d_out;

    int B = in_sizes[0] / (CHN * 64);   // 4096

    init_pack<<<1, 256>>>(w1, w2, w3, w4, f1, f2, f3, f4);
    spectral_kernel<<<B * 8, NT>>>(x, out,
                                   ln1w, ln1b, ln2w, ln2b,
                                   ln3w, ln3b, ln4w, ln4b);
}

// round 17
// speedup vs baseline: 1.7541x; 1.0684x over previous
#include <cuda_runtime.h>
#include <math.h>

#define CHN 143
#define NT  128

// Packed weights (float4 per (cout,cin) triple, 4th lane = 0) + twiddles.
// Layout (float4 units): W1@0(32), W2@32(448), W3@480(784), W4@1264(784),
//                        F1@2048(8), F2@2056(16), F3@2072(16), F4@2088(16)
__device__ float4 g_Wp[2104];
__device__ float2 g_tw[144];

__device__ __forceinline__ void copy3(float* dst, const float* src) {
    dst[0] = src[0]; dst[1] = src[1]; dst[2] = src[2]; dst[3] = 0.f;
}

__global__ void init_pack(const float* w1, const float* w2, const float* w3, const float* w4,
                          const float* f1, const float* f2, const float* f3, const float* f4)
{
    int tid = threadIdx.x;
    float* g = (float*)g_Wp;
    for (int e = tid; e < 32;  e += 256) copy3(g + (0    + e) * 4, w1 + e * 3);
    for (int e = tid; e < 448; e += 256) copy3(g + (32   + e) * 4, w2 + e * 3);
    for (int e = tid; e < 784; e += 256) copy3(g + (480  + e) * 4, w3 + e * 3);
    for (int e = tid; e < 784; e += 256) copy3(g + (1264 + e) * 4, w4 + e * 3);
    for (int e = tid; e < 8;   e += 256) copy3(g + (2048 + e) * 4, f1 + e * 3);
    for (int e = tid; e < 16;  e += 256) copy3(g + (2056 + e) * 4, f2 + e * 3);
    for (int e = tid; e < 16;  e += 256) copy3(g + (2072 + e) * 4, f3 + e * 3);
    for (int e = tid; e < 16;  e += 256) copy3(g + (2088 + e) * 4, f4 + e * 3);
    if (tid < 143) {
        double a = -2.0 * 3.14159265358979323846 * (double)tid / 143.0;
        g_tw[tid] = make_float2((float)cos(a), (float)sin(a));
    }
}

__device__ __forceinline__ float2 cmul(float2 a, float2 b) {
    return make_float2(fmaf(a.x, b.x, -a.y * b.y), fmaf(a.x, b.y, a.y * b.x));
}

// Pair-of-outputs conv (stages 1-2, Lout > 32): lane owns outputs (2P, 2P+1),
// P = lane + 32p. One LDS.128 gives row[4P..4P+3]; straddle element via shuffle.
// RowStride must be a multiple of 4 floats.
template<int Cin, int Cout, int RowStride, int Lout, int NP, int M>
__device__ __forceinline__ void convP(
    const float* __restrict__ in, int inStride,
    float* __restrict__ out, int outRow, int outStride,
    const float4* __restrict__ Wp,
    const float* __restrict__ gam, const float* __restrict__ bet,
    int warp, int lane)
{
    constexpr int ROWS  = Cout / 4;
    constexpr int LOADP = RowStride / 4;
    float a0[ROWS][M][NP], a1[ROWS][M][NP];
#pragma unroll
    for (int r = 0; r < ROWS; r++)
#pragma unroll
        for (int m = 0; m < M; m++)
#pragma unroll
            for (int p = 0; p < NP; p++) { a0[r][m][p] = 0.f; a1[r][m][p] = 0.f; }

#pragma unroll 2
    for (int ic = 0; ic < Cin; ic++) {
        float4 v[M][NP]; float ev[M][NP];
#pragma unroll
        for (int m = 0; m < M; m++) {
            const float* row = in + m * inStride + ic * RowStride;
#pragma unroll
            for (int p = 0; p < NP; p++) {
                int P = lane + 32 * p;
                v[m][p] = (P < LOADP) ? *(const float4*)(row + 4 * P)
                                      : make_float4(0.f, 0.f, 0.f, 0.f);
            }
        }
#pragma unroll
        for (int m = 0; m < M; m++)
#pragma unroll
            for (int p = 0; p < NP; p++) {
                float dn = __shfl_down_sync(0xffffffffu, v[m][p].x, 1);
                if (NP > 1) {
                    float nx = __shfl_sync(0xffffffffu,
                                           (p + 1 < NP) ? v[m][p + 1].x : 0.f, 0);
                    ev[m][p] = (lane == 31) ? nx : dn;
                } else {
                    ev[m][p] = dn;
                }
            }
#pragma unroll
        for (int r = 0; r < ROWS; r++) {
            int c = warp + 4 * r;
            float4 w = __ldg(Wp + c * Cin + ic);
#pragma unroll
            for (int m = 0; m < M; m++)
#pragma unroll
                for (int p = 0; p < NP; p++) {
                    a0[r][m][p] = fmaf(w.x, v[m][p].x, a0[r][m][p]);
                    a0[r][m][p] = fmaf(w.y, v[m][p].y, a0[r][m][p]);
                    a0[r][m][p] = fmaf(w.z, v[m][p].z, a0[r][m][p]);
                    a1[r][m][p] = fmaf(w.x, v[m][p].z, a1[r][m][p]);
                    a1[r][m][p] = fmaf(w.y, v[m][p].w, a1[r][m][p]);
                    a1[r][m][p] = fmaf(w.z, ev[m][p],  a1[r][m][p]);
                }
        }
    }

    float g0[NP], g1[NP], b0[NP], b1[NP];
#pragma unroll
    for (int p = 0; p < NP; p++) {
        int l = 2 * (lane + 32 * p);
        g0[p] = (l     < Lout) ? __ldg(gam + l)     : 0.f;
        b0[p] = (l     < Lout) ? __ldg(bet + l)     : 0.f;
        g1[p] = (l + 1 < Lout) ? __ldg(gam + l + 1) : 0.f;
        b1[p] = (l + 1 < Lout) ? __ldg(bet + l + 1) : 0.f;
    }
    const float invL = 1.0f / (float)Lout;

#pragma unroll
    for (int r = 0; r < ROWS; r++) {
        int c = warp + 4 * r;
#pragma unroll
        for (int m = 0; m < M; m++) {
            float s = 0.f;
#pragma unroll
            for (int p = 0; p < NP; p++) {
                int l = 2 * (lane + 32 * p);
                if (l     < Lout) s += a0[r][m][p];
                if (l + 1 < Lout) s += a1[r][m][p];
            }
#pragma unroll
            for (int o = 16; o; o >>= 1) s += __shfl_xor_sync(0xffffffffu, s, o);
            float mu = s * invL;

            float s2 = 0.f;
#pragma unroll
            for (int p = 0; p < NP; p++) {
                int l = 2 * (lane + 32 * p);
                if (l < Lout)     { float d = a0[r][m][p] - mu; s2 = fmaf(d, d, s2); }
                if (l + 1 < Lout) { float d = a1[r][m][p] - mu; s2 = fmaf(d, d, s2); }
            }
#pragma unroll
            for (int o = 16; o; o >>= 1) s2 += __shfl_xor_sync(0xffffffffu, s2, o);
            float inv = rsqrtf(fmaf(s2, invL, 1e-5f));

            float* orow = out + m * outStride + c * outRow;
#pragma unroll
            for (int p = 0; p < NP; p++) {
                int P = lane + 32 * p;
                int l = 2 * P;
                float o0 = fmaxf(fmaf((a0[r][m][p] - mu) * inv, g0[p], b0[p]), 0.f);
                float o1 = fmaxf(fmaf((a1[r][m][p] - mu) * inv, g1[p], b1[p]), 0.f);
                if (l + 1 < Lout) {
                    float2 t; t.x = o0; t.y = o1;
                    *(float2*)(orow + l) = t;
                } else if (l < Lout) {
                    orow[l] = o0;
                }
            }
        }
    }
}

// Single-output-per-lane conv (stage 3, Lout <= 30): float2 load + shuffle for
// the straddle element (lanes <= Lout load; x2 = next lane's x0).
template<int Cin, int Cout, int Sin, int Lout, int M>
__device__ __forceinline__ void convS(
    const float* __restrict__ in, int inStride,
    float* __restrict__ out, int Sout, int outStride,
    const float4* __restrict__ Wp,
    const float* __restrict__ gam, const float* __restrict__ bet,
    int warp, int lane)
{
    constexpr int ROWS = Cout / 4;
    float acc[ROWS][M];
#pragma unroll
    for (int r = 0; r < ROWS; r++)
#pragma unroll
        for (int m = 0; m < M; m++) acc[r][m] = 0.f;

#pragma unroll 2
    for (int ic = 0; ic < Cin; ic++) {
        float x0[M], x1[M], x2[M];
#pragma unroll
        for (int m = 0; m < M; m++) {
            const float* row = in + m * inStride + ic * Sin;
            if (lane <= Lout) {           // lane Lout supplies straddle via shfl
                float2 p = *(const float2*)(row + 2 * lane);
                x0[m] = p.x; x1[m] = p.y;
            } else { x0[m] = 0.f; x1[m] = 0.f; }
            x2[m] = __shfl_down_sync(0xffffffffu, x0[m], 1);
        }
#pragma unroll
        for (int r = 0; r < ROWS; r++) {
            int c = warp + 4 * r;
            float4 w = __ldg(Wp + c * Cin + ic);
#pragma unroll
            for (int m = 0; m < M; m++) {
                acc[r][m] = fmaf(w.x, x0[m], acc[r][m]);
                acc[r][m] = fmaf(w.y, x1[m], acc[r][m]);
                acc[r][m] = fmaf(w.z, x2[m], acc[r][m]);
            }
        }
    }

    float gv = (lane < Lout) ? __ldg(gam + lane) : 0.f;
    float bv = (lane < Lout) ? __ldg(bet + lane) : 0.f;
    const float invL = 1.0f / (float)Lout;

#pragma unroll
    for (int r = 0; r < ROWS; r++) {
        int c = warp + 4 * r;
#pragma unroll
        for (int m = 0; m < M; m++) {
            float s = (lane < Lout) ? acc[r][m] : 0.f;
#pragma unroll
            for (int o = 16; o; o >>= 1) s += __shfl_xor_sync(0xffffffffu, s, o);
            float mu = s * invL;

            float s2 = 0.f;
            if (lane < Lout) { float d = acc[r][m] - mu; s2 = d * d; }
#pragma unroll
            for (int o = 16; o; o >>= 1) s2 += __shfl_xor_sync(0xffffffffu, s2, o);
            float inv = rsqrtf(fmaf(s2, invL, 1e-5f));

            if (lane < Lout) {
                float val = (acc[r][m] - mu) * inv;
                out[m * outStride + c * Sout + lane] = fmaxf(fmaf(val, gv, bv), 0.f);
            }
        }
    }
}

// Stage-4 conv (Lout = 8): 4 samples packed into one warp. lane = s*8 + j.
// All 32 lanes productive; LN reduction over width-8 shuffle groups.
template<int Cin, int Cout, int Sin>
__device__ __forceinline__ void convS4(
    const float* __restrict__ in, int inStride,
    float* __restrict__ out, int Sout, int outStride,
    const float4* __restrict__ Wp,
    const float* __restrict__ gam, const float* __restrict__ bet,
    int warp, int lane)
{
    constexpr int ROWS = Cout / 4;
    int s4 = lane >> 3, j = lane & 7;
    const float* basep = in + s4 * inStride + 2 * j;
    float acc[ROWS];
#pragma unroll
    for (int r = 0; r < ROWS; r++) acc[r] = 0.f;

#pragma unroll 4
    for (int ic = 0; ic < Cin; ic++) {
        const float* row = basep + ic * Sin;
        float2 p = *(const float2*)row;   // elements 2j, 2j+1 (8B aligned)
        float x2 = row[2];                // element 2j+2 (max index 16 < Sin)
#pragma unroll
        for (int r = 0; r < ROWS; r++) {
            int c = warp + 4 * r;
            float4 w = __ldg(Wp + c * Cin + ic);
            acc[r] = fmaf(w.x, p.x, acc[r]);
            acc[r] = fmaf(w.y, p.y, acc[r]);
            acc[r] = fmaf(w.z, x2,  acc[r]);
        }
    }

    float gv = __ldg(gam + j);
    float bv = __ldg(bet + j);
    const float invL = 0.125f;

#pragma unroll
    for (int r = 0; r < ROWS; r++) {
        int c = warp + 4 * r;
        float s = acc[r];
#pragma unroll
        for (int o = 4; o; o >>= 1) s += __shfl_xor_sync(0xffffffffu, s, o);
        float mu = s * invL;

        float d = acc[r] - mu;
        float s2 = d * d;
#pragma unroll
        for (int o = 4; o; o >>= 1) s2 += __shfl_xor_sync(0xffffffffu, s2, o);
        float inv = rsqrtf(fmaf(s2, invL, 1e-5f));

        float val = (acc[r] - mu) * inv;
        out[s4 * outStride + c * Sout + j] = fmaxf(fmaf(val, gv, bv), 0.f);
    }
}

// Block = (b, stream, m-half): processes MB=4 samples.
#define MB 4
#define RAW_S 288    // per-sample raw/fold/vin stride (2 x 144)
#define A_S   1152   // 16*72 stage-1 output
#define B_S   1008   // 28*36 stage-2 output
#define C_S   504    // 28*18 stage-3 output
#define D_S   224    // 28*8  stage-4 output

__global__ void __launch_bounds__(NT, 5)
spectral_kernel(const float* __restrict__ x, float* __restrict__ out,
                const float* __restrict__ ln1w, const float* __restrict__ ln1b,
                const float* __restrict__ ln2w, const float* __restrict__ ln2b,
                const float* __restrict__ ln3w, const float* __restrict__ ln3b,
                const float* __restrict__ ln4w, const float* __restrict__ ln4b)
{
    __shared__ __align__(16) float  bufA[MB * A_S];   // 18432 B
    __shared__ __align__(16) float  bufB[MB * B_S];   // 16128 B
    __shared__ __align__(16) float2 twl[144];         // 1152 B
    // raw/vin/fold alias into bufB: all dead before stage 2 writes bufB.
    float* raw_s  = bufB;                   // MB*288 floats [0,1152)
    float* vin_s  = bufB + MB * RAW_S;      // MB*288 floats [1152,2304)
    float* fold_s = bufB + 2 * MB * RAW_S;  // MB*288 floats [2304,3456) <= 4032

    int tid  = threadIdx.x;
    int lane = tid & 31, warp = tid >> 5;
    unsigned blk = blockIdx.x;
    int b      = (int)(blk >> 3);
    int rem    = (int)(blk & 7);
    int stream = rem >> 1;         // 0=cr, 1=cc, 2=cr_fft, 3=cc_fft
    int mbase  = (rem & 1) * MB;   // 0 or 4
    bool isfft = (stream >= 2);
    bool isrow = (stream == 0 || stream == 2);

    const float* xb = x + (size_t)b * (CHN * 64);

    // ---- gather MB (2,143) samples into smem ----
    if (isrow) {
        // cr/cr_fft: the block's 4 samples (wp=0..3, c=0..1) are exactly the 8
        // consecutive floats x[b][ch][3+hh][0..7]: two LDG.128 per channel.
        int rowoff = (3 + (mbase >> 2)) * 8;
        for (int ch = tid; ch < 143; ch += NT) {
            const float* src = xb + ch * 64 + rowoff;
            float4 v0 = *(const float4*)(src);
            float4 v1 = *(const float4*)(src + 4);
            raw_s[0 * RAW_S +       ch] = v0.x;
            raw_s[0 * RAW_S + 144 + ch] = v0.y;
            raw_s[1 * RAW_S +       ch] = v0.z;
            raw_s[1 * RAW_S + 144 + ch] = v0.w;
            raw_s[2 * RAW_S +       ch] = v1.x;
            raw_s[2 * RAW_S + 144 + ch] = v1.y;
            raw_s[3 * RAW_S +       ch] = v1.z;
            raw_s[3 * RAW_S + 144 + ch] = v1.w;
        }
    } else {
        // cc/cc_fft: sample m -> h = m, channels w = 3 + c (scattered rows)
        for (int t = tid; t < MB * 286; t += NT) {
            int s = t / 286; int q = t - s * 286;
            int c = (q >= 143); int ch = q - 143 * c;
            int m = mbase + s;
            raw_s[s * RAW_S + c * 144 + ch] = __ldg(xb + ch * 64 + m * 8 + 3 + c);
        }
    }
    if (isfft) {
        for (int t = tid; t < 143; t += NT) twl[t] = g_tw[t];
    }
    __syncthreads();

    // ---- DFT magnitude via folding + 4-chain rotation (fft streams only) ----
    // fold slot n (0..71) per (s,c): n=0 -> (x0, 0); else (x[n]+x[143-n], x[n]-x[143-n]).
    // X[k] = sum_n rot(nk).x * fold.x  - i-part via rot.y * fold.y, rot = w^k chains.
    if (isfft) {
        for (int t = tid; t < MB * 144; t += NT) {
            int s = t / 144; int q = t - s * 144;
            int c = (q >= 72); int n = q - 72 * c;
            const float* v = raw_s + s * RAW_S + c * 144;
            float2 r;
            if (n == 0) r = make_float2(v[0], 0.f);
            else        r = make_float2(v[n] + v[143 - n], v[n] - v[143 - n]);
            ((float2*)(fold_s + s * RAW_S + c * 144))[n] = r;
        }
        __syncthreads();
        for (int t = tid; t < MB * 144; t += NT) {
            int s = t / 144; int u = t - s * 144;
            int c = (u >= 72); int k = u - 72 * c;
            const float2* f = (const float2*)(fold_s + s * RAW_S + c * 144);
            float2 w1 = twl[k];                 // one scattered LDS per bin
            float2 w2 = cmul(w1, w1);
            float2 w3 = cmul(w2, w1);
            float2 w4 = cmul(w2, w2);
            float2 r0 = make_float2(1.f, 0.f), r1 = w1, r2 = w2, r3 = w3;
            float re = 0.f, im = 0.f;
#pragma unroll 6
            for (int st = 0; st < 18; st++) {
                float4 fa = *(const float4*)(f + 4 * st);
                float4 fb = *(const float4*)(f + 4 * st + 2);
                re = fmaf(r0.x, fa.x, re); im = fmaf(r0.y, fa.y, im);
                re = fmaf(r1.x, fa.z, re); im = fmaf(r1.y, fa.w, im);
                re = fmaf(r2.x, fb.x, re); im = fmaf(r2.y, fb.y, im);
                re = fmaf(r3.x, fb.z, re); im = fmaf(r3.y, fb.w, im);
                r0 = cmul(r0, w4); r1 = cmul(r1, w4);
                r2 = cmul(r2, w4); r3 = cmul(r3, w4);
            }
            float mag = sqrtf(fmaf(re, re, im * im));
            float* vp = vin_s + s * RAW_S + c * 144;
            vp[k] = mag;
            if (k) vp[143 - k] = mag;
        }
        __syncthreads();
    }

    const float* cin = isfft ? vin_s : raw_s;

    if (!isfft) {
#pragma unroll
        for (int s = 0; s < MB; s++)
            convP<2, 16, 144, 71, 2, 1>(cin + s * RAW_S, RAW_S,
                                        bufA + s * A_S, 72, A_S,
                                        g_Wp + 0, ln1w, ln1b, warp, lane);
        __syncthreads();
        convP<16, 28, 72, 35, 1, MB>(bufA, A_S, bufB, 36, B_S,
                                     g_Wp + 32,   ln2w, ln2b, warp, lane);
        __syncthreads();
        convS<28, 28, 36, 17, MB>(bufB, B_S, bufA, 18, C_S,
                                  g_Wp + 480,  ln3w, ln3b, warp, lane);
        __syncthreads();
        convS4<28, 28, 18>(bufA, C_S, bufB, 8, D_S,
                           g_Wp + 1264, ln4w, ln4b, warp, lane);
        __syncthreads();
        int cbase = stream * 28;                       // 0 or 28
        size_t obase = (size_t)b * 4096 + (size_t)cbase * 64;
        for (int t = tid; t < MB * 112; t += NT) {
            int s = t / 112; int q = t - s * 112;
            int c = q >> 2, jj = q & 3;
            float2 v = *(const float2*)(bufB + s * D_S + c * 8 + 2 * jj);
            *(float2*)(out + obase + (size_t)c * 64 + (size_t)(mbase + s) * 8 + 2 * jj) = v;
        }
    } else {
#pragma unroll
        for (int s = 0; s < MB; s++)
            convP<2, 4, 144, 71, 2, 1>(cin + s * RAW_S, RAW_S,
                                       bufA + s * A_S, 72, A_S,
                                       g_Wp + 2048, ln1w, ln1b, warp, lane);
        __syncthreads();
        convP<4, 4, 72, 35, 1, MB>(bufA, A_S, bufB, 36, B_S,
                                   g_Wp + 2056, ln2w, ln2b, warp, lane);
        __syncthreads();
        convS<4, 4, 36, 17, MB>(bufB, B_S, bufA, 18, C_S,
                                g_Wp + 2072, ln3w, ln3b, warp, lane);
        __syncthreads();
        convS4<4, 4, 18>(bufA, C_S, bufB, 8, D_S,
                         g_Wp + 2088, ln4w, ln4b, warp, lane);
        __syncthreads();
        int cbase = 56 + (stream - 2) * 4;             // 56 or 60
        size_t obase = (size_t)b * 4096 + (size_t)cbase * 64;
        for (int t = tid; t < MB * 16; t += NT) {
            int s = t >> 4; int q = t & 15;
            int c = q >> 2, jj = q & 3;
            float2 v = *(const float2*)(bufB + s * D_S + c * 8 + 2 * jj);
            *(float2*)(out + obase + (size_t)c * 64 + (size_t)(mbase + s) * 8 + 2 * jj) = v;
        }
    }
}

extern "C" void kernel_launch(void* const* d_in, const int* in_sizes, int n_in,
                              void* d_out, int out_size)
{
    const float* x   = (const float*)d_in[0];
    const float* w1  = (const float*)d_in[1];
    const float* w2  = (const float*)d_in[2];
    const float* w3  = (const float*)d_in[3];
    const float* w4  = (const float*)d_in[4];
    const float* f1  = (const float*)d_in[5];
    const float* f2  = (const float*)d_in[6];
    const float* f3  = (const float*)d_in[7];
    const float* f4  = (const float*)d_in[8];
    const float* ln1w = (const float*)d_in[9];
    const float* ln1b = (const float*)d_in[10];
    const float* ln2w = (const float*)d_in[11];
    const float* ln2b = (const float*)d_in[12];
    const float* ln3w = (const float*)d_in[13];
    const float* ln3b = (const float*)d_in[14];
    const float* ln4w = (const float*)d_in[15];
    const float* ln4b = (const float*)d_in[16];
    float* out = (float*)d_out;

    int B = in_sizes[0] / (CHN * 64);   // 4096

    init_pack<<<1, 256>>>(w1, w2, w3, w4, f1, f2, f3, f4);
    spectral_kernel<<<B * 8, NT>>>(x, out,
                                   ln1w, ln1b, ln2w, ln2b,
                                   ln3w, ln3b, ln4w, ln4b);
}